// round 7
// baseline (speedup 1.0000x reference)
#include <cuda_runtime.h>
#include <cuda_bf16.h>

#define NUSR 100000
#define NTXN 400000
#define NEDG 400000
#define HDIM 128
#define NLAY 3
#define HID2 64
#define OUTD 2
#define EPSV 1e-5f

// ---------------- scratch (device globals; no runtime allocation) ----------------
__device__ float g_hu[(size_t)NUSR * HDIM];     //  51.2 MB
__device__ float g_ht[(size_t)NTXN * HDIM];     // 204.8 MB
__device__ float g_aggu[(size_t)NUSR * HDIM];   //  51.2 MB
__device__ float g_aggt[(size_t)NTXN * HDIM];   // 204.8 MB
__device__ float g_invu[NUSR];
__device__ float g_invt[NTXN];
__device__ int   g_cntu[NUSR];
__device__ int   g_cntt[NTXN];

// ---------------- small utility kernels ----------------
__global__ void zero_f4(float4* __restrict__ p, int n4) {
    int i = blockIdx.x * blockDim.x + threadIdx.x;
    if (i < n4) p[i] = make_float4(0.f, 0.f, 0.f, 0.f);
}

// h[n,:] = emb[idx[n],:]  (one warp per row, float4 per lane)
__global__ void gather_emb(const int* __restrict__ idx,
                           const float* __restrict__ emb,
                           float* __restrict__ out, int n) {
    int t = blockIdx.x * blockDim.x + threadIdx.x;
    int row = t >> 5, lane = t & 31;
    if (row >= n) return;
    int src = __ldg(idx + row);
    float4 v = __ldg((const float4*)(emb + (size_t)src * HDIM) + lane);
    ((float4*)(out + (size_t)row * HDIM))[lane] = v;
}

__global__ void count_deg(const int* __restrict__ dst, int* __restrict__ cnt, int n) {
    int i = blockIdx.x * blockDim.x + threadIdx.x;
    if (i < n) atomicAdd(&cnt[__ldg(dst + i)], 1);
}

__global__ void make_inv(const int* __restrict__ cnt, float* __restrict__ inv, int n) {
    int i = blockIdx.x * blockDim.x + threadIdx.x;
    if (i < n) {
        int c = cnt[i];
        inv[i] = 1.0f / (float)(c > 1 ? c : 1);
    }
}

// one warp per edge: agg[dst] += feat[src]  (vector f32x4 reduction, no return)
__global__ void scatter_add(const int* __restrict__ src, const int* __restrict__ dst,
                            const float* __restrict__ feat, float* __restrict__ agg, int n) {
    int t = blockIdx.x * blockDim.x + threadIdx.x;
    int e = t >> 5, lane = t & 31;
    if (e >= n) return;
    int s = __ldg(src + e);
    int d = __ldg(dst + e);
    float4 v = __ldg((const float4*)(feat + (size_t)s * HDIM) + lane);
    float* a = agg + (size_t)d * HDIM + lane * 4;
    asm volatile("red.global.add.v4.f32 [%0], {%1,%2,%3,%4};"
                 :: "l"(a), "f"(v.x), "f"(v.y), "f"(v.z), "f"(v.w) : "memory");
}

// ---------------- fused dual GEMM + bias + BN + ReLU (in place) ----------------
// out[m,:] = relu( BN( (A1[m,:]*inv[m]) @ Wl + bias + A2[m,:] @ Wr ) ),  out == A2 allowed
// tile: 64 rows x 128 cols, 256 threads, each thread 8 rows x 4 cols
__global__ __launch_bounds__(256) void gemm_fused(
    const float* __restrict__ A1, const float* __restrict__ inv,
    const float* __restrict__ A2,
    const float* __restrict__ Wl, const float* __restrict__ Wr,
    const float* __restrict__ bias,
    const float* __restrict__ gma, const float* __restrict__ bta,
    const float* __restrict__ mu,  const float* __restrict__ var,
    float* __restrict__ out, int M)
{
    extern __shared__ float smem[];           // 2 * 64*128 floats = 64 KB
    float* sA1 = smem;
    float* sA2 = smem + 64 * HDIM;

    const int tid  = threadIdx.x;
    const int row0 = blockIdx.x * 64;

    // stage A tiles (A1 pre-scaled by inverse degree)
    for (int i = tid; i < 64 * 32; i += 256) {
        int r = i >> 5, c = (i & 31) * 4;
        int row = row0 + r;
        float4 v1 = make_float4(0.f, 0.f, 0.f, 0.f), v2 = v1;
        if (row < M) {
            v1 = __ldg((const float4*)(A1 + (size_t)row * HDIM + c));
            float s = __ldg(inv + row);
            v1.x *= s; v1.y *= s; v1.z *= s; v1.w *= s;
            v2 = __ldg((const float4*)(A2 + (size_t)row * HDIM + c));
        }
        *(float4*)&sA1[r * HDIM + c] = v1;
        *(float4*)&sA2[r * HDIM + c] = v2;
    }
    __syncthreads();

    const int lane = tid & 31;
    const int rb   = (tid >> 5) * 8;   // 8 warps * 8 rows
    const int col  = lane * 4;

    float acc[8][4];
    #pragma unroll
    for (int i = 0; i < 8; i++)
        #pragma unroll
        for (int j = 0; j < 4; j++) acc[i][j] = 0.f;

    #pragma unroll 4
    for (int k = 0; k < HDIM; k++) {
        float4 w1 = __ldg((const float4*)(Wl + k * HDIM + col));
        float4 w2 = __ldg((const float4*)(Wr + k * HDIM + col));
        #pragma unroll
        for (int i = 0; i < 8; i++) {
            float a1 = sA1[(rb + i) * HDIM + k];
            float a2 = sA2[(rb + i) * HDIM + k];
            acc[i][0] = fmaf(a1, w1.x, fmaf(a2, w2.x, acc[i][0]));
            acc[i][1] = fmaf(a1, w1.y, fmaf(a2, w2.y, acc[i][1]));
            acc[i][2] = fmaf(a1, w1.z, fmaf(a2, w2.z, acc[i][2]));
            acc[i][3] = fmaf(a1, w1.w, fmaf(a2, w2.w, acc[i][3]));
        }
    }

    // epilogue: y = relu( (acc + bias - mean) * rsqrt(var+eps)*gamma + beta )
    float scl[4], sft[4];
    #pragma unroll
    for (int j = 0; j < 4; j++) {
        int c = col + j;
        float rs = rsqrtf(__ldg(var + c) + EPSV) * __ldg(gma + c);
        scl[j] = rs;
        sft[j] = __ldg(bta + c) + (__ldg(bias + c) - __ldg(mu + c)) * rs;
    }
    #pragma unroll
    for (int i = 0; i < 8; i++) {
        int row = row0 + rb + i;
        if (row < M) {
            float4 o;
            o.x = fmaxf(fmaf(acc[i][0], scl[0], sft[0]), 0.f);
            o.y = fmaxf(fmaf(acc[i][1], scl[1], sft[1]), 0.f);
            o.z = fmaxf(fmaf(acc[i][2], scl[2], sft[2]), 0.f);
            o.w = fmaxf(fmaf(acc[i][3], scl[3], sft[3]), 0.f);
            *(float4*)(out + (size_t)row * HDIM + col) = o;
        }
    }
}

// ---------------- fused MLP head: out = relu(h@W1+b1)@W2+b2 ----------------
// one warp per node row; W1 in smem; h broadcast via shfl
// NOTE: lane kk's hb[j] is h[kk*4 + j]  (float4 layout), so W1 row index is kk*4+j.
__global__ __launch_bounds__(256) void mlp_head(
    const float* __restrict__ hu, const float* __restrict__ ht,
    const float* __restrict__ W1, const float* __restrict__ b1,
    const float* __restrict__ W2, const float* __restrict__ b2,
    float* __restrict__ out)
{
    __shared__ float sW1[HDIM * HID2];   // 32 KB
    __shared__ float sb1[HID2];
    __shared__ float sW2[HID2 * OUTD];
    for (int i = threadIdx.x; i < HDIM * HID2; i += 256) sW1[i] = W1[i];
    if (threadIdx.x < HID2) sb1[threadIdx.x] = b1[threadIdx.x];
    if (threadIdx.x < HID2 * OUTD) sW2[threadIdx.x] = W2[threadIdx.x];
    __syncthreads();

    int gw   = (blockIdx.x * 256 + threadIdx.x) >> 5;
    int lane = threadIdx.x & 31;
    if (gw >= NUSR + NTXN) return;

    const float* hrow = (gw < NUSR) ? hu + (size_t)gw * HDIM
                                    : ht + (size_t)(gw - NUSR) * HDIM;
    float4 hv = __ldg((const float4*)hrow + lane);
    float hb[4] = {hv.x, hv.y, hv.z, hv.w};

    float acc0 = 0.f, acc1 = 0.f;
    #pragma unroll
    for (int j = 0; j < 4; j++) {
        #pragma unroll
        for (int kk = 0; kk < 32; kk++) {
            float hk = __shfl_sync(0xffffffffu, hb[j], kk);
            int k = kk * 4 + j;   // FIX: element held by lane kk slot j is h[kk*4+j]
            acc0 = fmaf(hk, sW1[k * HID2 + lane],      acc0);
            acc1 = fmaf(hk, sW1[k * HID2 + lane + 32], acc1);
        }
    }
    float h0 = fmaxf(acc0 + sb1[lane],      0.f);
    float h1 = fmaxf(acc1 + sb1[lane + 32], 0.f);
    float o0 = h0 * sW2[lane * OUTD + 0] + h1 * sW2[(lane + 32) * OUTD + 0];
    float o1 = h0 * sW2[lane * OUTD + 1] + h1 * sW2[(lane + 32) * OUTD + 1];
    #pragma unroll
    for (int off = 16; off > 0; off >>= 1) {
        o0 += __shfl_down_sync(0xffffffffu, o0, off);
        o1 += __shfl_down_sync(0xffffffffu, o1, off);
    }
    if (lane == 0) {
        out[(size_t)gw * OUTD + 0] = o0 + __ldg(b2 + 0);
        out[(size_t)gw * OUTD + 1] = o1 + __ldg(b2 + 1);
    }
}

// ---------------- launcher ----------------
extern "C" void kernel_launch(void* const* d_in, const int* in_sizes, int n_in,
                              void* d_out, int out_size) {
    (void)in_sizes; (void)n_in; (void)out_size;
    const int*   x_user  = (const int*)  d_in[0];
    const int*   x_txn   = (const int*)  d_in[1];
    const int*   ei0_src = (const int*)  d_in[2];
    const int*   ei0_dst = (const int*)  d_in[3];
    const int*   ei1_src = (const int*)  d_in[4];
    const int*   ei1_dst = (const int*)  d_in[5];
    const float* emb_u   = (const float*)d_in[6];
    const float* emb_t   = (const float*)d_in[7];
    const float* Wl      = (const float*)d_in[8];
    const float* bl      = (const float*)d_in[9];
    const float* Wr      = (const float*)d_in[10];
    const float* bn_g    = (const float*)d_in[11];
    const float* bn_b    = (const float*)d_in[12];
    const float* bn_m    = (const float*)d_in[13];
    const float* bn_v    = (const float*)d_in[14];
    const float* W1      = (const float*)d_in[15];
    const float* b1      = (const float*)d_in[16];
    const float* W2      = (const float*)d_in[17];
    const float* b2      = (const float*)d_in[18];
    float* out = (float*)d_out;

    float *hu, *ht, *aggu, *aggt, *invu, *invt;
    int *cntu, *cntt;
    cudaGetSymbolAddress((void**)&hu,   g_hu);
    cudaGetSymbolAddress((void**)&ht,   g_ht);
    cudaGetSymbolAddress((void**)&aggu, g_aggu);
    cudaGetSymbolAddress((void**)&aggt, g_aggt);
    cudaGetSymbolAddress((void**)&invu, g_invu);
    cudaGetSymbolAddress((void**)&invt, g_invt);
    cudaGetSymbolAddress((void**)&cntu, g_cntu);
    cudaGetSymbolAddress((void**)&cntt, g_cntt);

    const int GEMM_SMEM = 2 * 64 * HDIM * (int)sizeof(float);  // 64 KB
    cudaFuncSetAttribute(gemm_fused, cudaFuncAttributeMaxDynamicSharedMemorySize, GEMM_SMEM);

    // 1) embedding gather
    gather_emb<<<(NUSR * 32 + 255) / 256, 256>>>(x_user, emb_u, hu, NUSR);
    gather_emb<<<(NTXN * 32 + 255) / 256, 256>>>(x_txn,  emb_t, ht, NTXN);

    // 2) degree counts (layer-invariant) -> reciprocals
    zero_f4<<<(NTXN / 4 + 255) / 256, 256>>>((float4*)cntt, NTXN / 4);
    zero_f4<<<(NUSR / 4 + 255) / 256, 256>>>((float4*)cntu, NUSR / 4);
    count_deg<<<(NEDG + 255) / 256, 256>>>(ei0_dst, cntt, NEDG);
    count_deg<<<(NEDG + 255) / 256, 256>>>(ei1_dst, cntu, NEDG);
    make_inv<<<(NTXN + 255) / 256, 256>>>(cntt, invt, NTXN);
    make_inv<<<(NUSR + 255) / 256, 256>>>(cntu, invu, NUSR);

    // 3) layers
    for (int l = 0; l < NLAY; l++) {
        zero_f4<<<(NTXN * (HDIM / 4) + 255) / 256, 256>>>((float4*)aggt, NTXN * (HDIM / 4));
        zero_f4<<<(NUSR * (HDIM / 4) + 255) / 256, 256>>>((float4*)aggu, NUSR * (HDIM / 4));

        scatter_add<<<(NEDG * 32 + 255) / 256, 256>>>(ei0_src, ei0_dst, hu, aggt, NEDG);
        scatter_add<<<(NEDG * 32 + 255) / 256, 256>>>(ei1_src, ei1_dst, ht, aggu, NEDG);

        const size_t HH = (size_t)HDIM * HDIM;
        // txn nodes: weights/bias index (l,0), BN index (l,1)
        gemm_fused<<<(NTXN + 63) / 64, 256, GEMM_SMEM>>>(
            aggt, invt, ht,
            Wl + (size_t)(l * 2 + 0) * HH, Wr + (size_t)(l * 2 + 0) * HH,
            bl   + (size_t)(l * 2 + 0) * HDIM,
            bn_g + (size_t)(l * 2 + 1) * HDIM, bn_b + (size_t)(l * 2 + 1) * HDIM,
            bn_m + (size_t)(l * 2 + 1) * HDIM, bn_v + (size_t)(l * 2 + 1) * HDIM,
            ht, NTXN);
        // user nodes: weights/bias index (l,1), BN index (l,0)
        gemm_fused<<<(NUSR + 63) / 64, 256, GEMM_SMEM>>>(
            aggu, invu, hu,
            Wl + (size_t)(l * 2 + 1) * HH, Wr + (size_t)(l * 2 + 1) * HH,
            bl   + (size_t)(l * 2 + 1) * HDIM,
            bn_g + (size_t)(l * 2 + 0) * HDIM, bn_b + (size_t)(l * 2 + 0) * HDIM,
            bn_m + (size_t)(l * 2 + 0) * HDIM, bn_v + (size_t)(l * 2 + 0) * HDIM,
            hu, NUSR);
    }

    // 4) MLP head
    mlp_head<<<((NUSR + NTXN) * 32 + 255) / 256, 256>>>(hu, ht, W1, b1, W2, b2, out);
}

// round 8
// speedup vs baseline: 1.2158x; 1.2158x over previous
#include <cuda_runtime.h>
#include <cuda_bf16.h>

#define NUSR 100000
#define NTXN 400000
#define NEDG 400000
#define HDIM 128
#define NLAY 3
#define HID2 64
#define OUTD 2
#define EPSV 1e-5f

typedef unsigned long long ull;

// ---------------- packed f32x2 helpers (sm_103a FFMA2 path) ----------------
__device__ __forceinline__ ull pk2(float x, float y) {
    ull r; asm("mov.b64 %0, {%1, %2};" : "=l"(r) : "f"(x), "f"(y)); return r;
}
__device__ __forceinline__ ull fma2(ull a, ull b, ull c) {
    ull d; asm("fma.rn.f32x2 %0, %1, %2, %3;" : "=l"(d) : "l"(a), "l"(b), "l"(c)); return d;
}
__device__ __forceinline__ float2 upk(ull v) {
    float2 r; asm("mov.b64 {%0, %1}, %2;" : "=f"(r.x), "=f"(r.y) : "l"(v)); return r;
}

// ---------------- scratch (device globals; no runtime allocation) ----------------
__device__ float g_hu[(size_t)NUSR * HDIM];
__device__ float g_ht[(size_t)NTXN * HDIM];
__device__ float g_aggu[(size_t)NUSR * HDIM];
__device__ float g_aggt[(size_t)NTXN * HDIM];
__device__ float g_invu[NUSR];
__device__ float g_invt[NTXN];
__device__ int   g_cntu[NUSR];
__device__ int   g_cntt[NTXN];

// ---------------- small utility kernels ----------------
__global__ void zero_f4(float4* __restrict__ p, int n4) {
    int i = blockIdx.x * blockDim.x + threadIdx.x;
    if (i < n4) p[i] = make_float4(0.f, 0.f, 0.f, 0.f);
}

__global__ void gather_emb(const int* __restrict__ idx,
                           const float* __restrict__ emb,
                           float* __restrict__ out, int n) {
    int t = blockIdx.x * blockDim.x + threadIdx.x;
    int row = t >> 5, lane = t & 31;
    if (row >= n) return;
    int src = __ldg(idx + row);
    float4 v = __ldg((const float4*)(emb + (size_t)src * HDIM) + lane);
    ((float4*)(out + (size_t)row * HDIM))[lane] = v;
}

__global__ void count_deg(const int* __restrict__ dst, int* __restrict__ cnt, int n) {
    int i = blockIdx.x * blockDim.x + threadIdx.x;
    if (i < n) atomicAdd(&cnt[__ldg(dst + i)], 1);
}

__global__ void make_inv(const int* __restrict__ cnt, float* __restrict__ inv, int n) {
    int i = blockIdx.x * blockDim.x + threadIdx.x;
    if (i < n) {
        int c = cnt[i];
        inv[i] = 1.0f / (float)(c > 1 ? c : 1);
    }
}

// one warp per edge: agg[dst] += feat[src]  (vector f32x4 reduction, no return)
__global__ void scatter_add(const int* __restrict__ src, const int* __restrict__ dst,
                            const float* __restrict__ feat, float* __restrict__ agg, int n) {
    int t = blockIdx.x * blockDim.x + threadIdx.x;
    int e = t >> 5, lane = t & 31;
    if (e >= n) return;
    int s = __ldg(src + e);
    int d = __ldg(dst + e);
    float4 v = __ldg((const float4*)(feat + (size_t)s * HDIM) + lane);
    float* a = agg + (size_t)d * HDIM + lane * 4;
    asm volatile("red.global.add.v4.f32 [%0], {%1,%2,%3,%4};"
                 :: "l"(a), "f"(v.x), "f"(v.y), "f"(v.z), "f"(v.w) : "memory");
}

// ---------------- fused dual GEMM + bias + BN + ReLU (in place, FFMA2) ----------------
// out[m,:] = relu( BN( (A1[m,:]*inv[m]) @ Wl + bias + A2[m,:] @ Wr ) ),  out == A2 allowed
// tile: 64 rows x 128 cols, 256 threads. Rows packed in pairs into f32x2 lanes.
// smem A layout: [32 pairs][128 k][2 halves] floats  (LDS.64 -> (a[r][k], a[r+1][k]))
__global__ __launch_bounds__(256) void gemm_fused(
    const float* __restrict__ A1, const float* __restrict__ inv,
    const float* __restrict__ A2,
    const float* __restrict__ Wl, const float* __restrict__ Wr,
    const float* __restrict__ bias,
    const float* __restrict__ gma, const float* __restrict__ bta,
    const float* __restrict__ mu,  const float* __restrict__ var,
    float* __restrict__ out, int M)
{
    extern __shared__ float smem[];           // 2 * 64*128 floats = 64 KB
    float* sA1 = smem;                        // pair-interleaved
    float* sA2 = smem + 64 * HDIM;

    const int tid  = threadIdx.x;
    const int row0 = blockIdx.x * 64;

    // ---- stage A tiles: pair-interleave rows, A1 pre-scaled by inverse degree ----
    // i indexes (pair p in [0,32), k-chunk kc in [0,64)); each chunk = 2 k values.
    for (int i = tid; i < 32 * 64; i += 256) {
        int p  = i >> 6;
        int kc = i & 63;
        int r0 = row0 + p * 2;
        int r1 = r0 + 1;
        float2 a0 = make_float2(0.f, 0.f), a1 = a0, b0 = a0, b1 = a0;
        float s0 = 0.f, s1 = 0.f;
        if (r0 < M) {
            a0 = __ldg((const float2*)(A1 + (size_t)r0 * HDIM + kc * 2));
            b0 = __ldg((const float2*)(A2 + (size_t)r0 * HDIM + kc * 2));
            s0 = __ldg(inv + r0);
        }
        if (r1 < M) {
            a1 = __ldg((const float2*)(A1 + (size_t)r1 * HDIM + kc * 2));
            b1 = __ldg((const float2*)(A2 + (size_t)r1 * HDIM + kc * 2));
            s1 = __ldg(inv + r1);
        }
        float4 v1 = make_float4(a0.x * s0, a1.x * s1, a0.y * s0, a1.y * s1);
        float4 v2 = make_float4(b0.x,      b1.x,      b0.y,      b1.y);
        *(float4*)&sA1[p * 256 + kc * 4] = v1;
        *(float4*)&sA2[p * 256 + kc * 4] = v2;
    }
    __syncthreads();

    const int lane = tid & 31;
    const int warp = tid >> 5;
    const int pb   = warp * 4;     // 4 row-pairs (8 rows) per warp
    const int col  = lane * 4;

    ull acc[4][4];
    #pragma unroll
    for (int p = 0; p < 4; p++)
        #pragma unroll
        for (int c = 0; c < 4; c++) acc[p][c] = 0ull;

    #pragma unroll 4
    for (int k = 0; k < HDIM; k++) {
        float4 w1 = __ldg((const float4*)(Wl + k * HDIM + col));
        float4 w2 = __ldg((const float4*)(Wr + k * HDIM + col));
        ull w1p[4] = { pk2(w1.x, w1.x), pk2(w1.y, w1.y), pk2(w1.z, w1.z), pk2(w1.w, w1.w) };
        ull w2p[4] = { pk2(w2.x, w2.x), pk2(w2.y, w2.y), pk2(w2.z, w2.z), pk2(w2.w, w2.w) };
        #pragma unroll
        for (int p = 0; p < 4; p++) {
            ull a1 = *(const ull*)&sA1[(pb + p) * 256 + k * 2];
            ull a2 = *(const ull*)&sA2[(pb + p) * 256 + k * 2];
            #pragma unroll
            for (int c = 0; c < 4; c++)
                acc[p][c] = fma2(a1, w1p[c], fma2(a2, w2p[c], acc[p][c]));
        }
    }

    // ---- epilogue: y = relu( acc*scl + sft ), scl/sft fold bias+BN ----
    float scl[4], sft[4];
    #pragma unroll
    for (int j = 0; j < 4; j++) {
        int c = col + j;
        float rs = rsqrtf(__ldg(var + c) + EPSV) * __ldg(gma + c);
        scl[j] = rs;
        sft[j] = __ldg(bta + c) + (__ldg(bias + c) - __ldg(mu + c)) * rs;
    }
    #pragma unroll
    for (int p = 0; p < 4; p++) {
        float2 u0 = upk(acc[p][0]);
        float2 u1 = upk(acc[p][1]);
        float2 u2 = upk(acc[p][2]);
        float2 u3 = upk(acc[p][3]);
        int r0 = row0 + warp * 8 + p * 2;
        if (r0 < M) {
            float4 o;
            o.x = fmaxf(fmaf(u0.x, scl[0], sft[0]), 0.f);
            o.y = fmaxf(fmaf(u1.x, scl[1], sft[1]), 0.f);
            o.z = fmaxf(fmaf(u2.x, scl[2], sft[2]), 0.f);
            o.w = fmaxf(fmaf(u3.x, scl[3], sft[3]), 0.f);
            *(float4*)(out + (size_t)r0 * HDIM + col) = o;
        }
        if (r0 + 1 < M) {
            float4 o;
            o.x = fmaxf(fmaf(u0.y, scl[0], sft[0]), 0.f);
            o.y = fmaxf(fmaf(u1.y, scl[1], sft[1]), 0.f);
            o.z = fmaxf(fmaf(u2.y, scl[2], sft[2]), 0.f);
            o.w = fmaxf(fmaf(u3.y, scl[3], sft[3]), 0.f);
            *(float4*)(out + (size_t)(r0 + 1) * HDIM + col) = o;
        }
    }
}

// ---------------- fused MLP head: out = relu(h@W1+b1)@W2+b2 ----------------
__global__ __launch_bounds__(256) void mlp_head(
    const float* __restrict__ hu, const float* __restrict__ ht,
    const float* __restrict__ W1, const float* __restrict__ b1,
    const float* __restrict__ W2, const float* __restrict__ b2,
    float* __restrict__ out)
{
    __shared__ float sW1[HDIM * HID2];   // 32 KB
    __shared__ float sb1[HID2];
    __shared__ float sW2[HID2 * OUTD];
    for (int i = threadIdx.x; i < HDIM * HID2; i += 256) sW1[i] = W1[i];
    if (threadIdx.x < HID2) sb1[threadIdx.x] = b1[threadIdx.x];
    if (threadIdx.x < HID2 * OUTD) sW2[threadIdx.x] = W2[threadIdx.x];
    __syncthreads();

    int gw   = (blockIdx.x * 256 + threadIdx.x) >> 5;
    int lane = threadIdx.x & 31;
    if (gw >= NUSR + NTXN) return;

    const float* hrow = (gw < NUSR) ? hu + (size_t)gw * HDIM
                                    : ht + (size_t)(gw - NUSR) * HDIM;
    float4 hv = __ldg((const float4*)hrow + lane);
    float hb[4] = {hv.x, hv.y, hv.z, hv.w};

    float acc0 = 0.f, acc1 = 0.f;
    #pragma unroll
    for (int j = 0; j < 4; j++) {
        #pragma unroll
        for (int kk = 0; kk < 32; kk++) {
            float hk = __shfl_sync(0xffffffffu, hb[j], kk);
            int k = kk * 4 + j;   // lane kk slot j holds h[kk*4+j]
            acc0 = fmaf(hk, sW1[k * HID2 + lane],      acc0);
            acc1 = fmaf(hk, sW1[k * HID2 + lane + 32], acc1);
        }
    }
    float h0 = fmaxf(acc0 + sb1[lane],      0.f);
    float h1 = fmaxf(acc1 + sb1[lane + 32], 0.f);
    float o0 = h0 * sW2[lane * OUTD + 0] + h1 * sW2[(lane + 32) * OUTD + 0];
    float o1 = h0 * sW2[lane * OUTD + 1] + h1 * sW2[(lane + 32) * OUTD + 1];
    #pragma unroll
    for (int off = 16; off > 0; off >>= 1) {
        o0 += __shfl_down_sync(0xffffffffu, o0, off);
        o1 += __shfl_down_sync(0xffffffffu, o1, off);
    }
    if (lane == 0) {
        out[(size_t)gw * OUTD + 0] = o0 + __ldg(b2 + 0);
        out[(size_t)gw * OUTD + 1] = o1 + __ldg(b2 + 1);
    }
}

// ---------------- launcher ----------------
extern "C" void kernel_launch(void* const* d_in, const int* in_sizes, int n_in,
                              void* d_out, int out_size) {
    (void)in_sizes; (void)n_in; (void)out_size;
    const int*   x_user  = (const int*)  d_in[0];
    const int*   x_txn   = (const int*)  d_in[1];
    const int*   ei0_src = (const int*)  d_in[2];
    const int*   ei0_dst = (const int*)  d_in[3];
    const int*   ei1_src = (const int*)  d_in[4];
    const int*   ei1_dst = (const int*)  d_in[5];
    const float* emb_u   = (const float*)d_in[6];
    const float* emb_t   = (const float*)d_in[7];
    const float* Wl      = (const float*)d_in[8];
    const float* bl      = (const float*)d_in[9];
    const float* Wr      = (const float*)d_in[10];
    const float* bn_g    = (const float*)d_in[11];
    const float* bn_b    = (const float*)d_in[12];
    const float* bn_m    = (const float*)d_in[13];
    const float* bn_v    = (const float*)d_in[14];
    const float* W1      = (const float*)d_in[15];
    const float* b1      = (const float*)d_in[16];
    const float* W2      = (const float*)d_in[17];
    const float* b2      = (const float*)d_in[18];
    float* out = (float*)d_out;

    float *hu, *ht, *aggu, *aggt, *invu, *invt;
    int *cntu, *cntt;
    cudaGetSymbolAddress((void**)&hu,   g_hu);
    cudaGetSymbolAddress((void**)&ht,   g_ht);
    cudaGetSymbolAddress((void**)&aggu, g_aggu);
    cudaGetSymbolAddress((void**)&aggt, g_aggt);
    cudaGetSymbolAddress((void**)&invu, g_invu);
    cudaGetSymbolAddress((void**)&invt, g_invt);
    cudaGetSymbolAddress((void**)&cntu, g_cntu);
    cudaGetSymbolAddress((void**)&cntt, g_cntt);

    const int GEMM_SMEM = 2 * 64 * HDIM * (int)sizeof(float);  // 64 KB
    cudaFuncSetAttribute(gemm_fused, cudaFuncAttributeMaxDynamicSharedMemorySize, GEMM_SMEM);

    // 1) embedding gather
    gather_emb<<<(NUSR * 32 + 255) / 256, 256>>>(x_user, emb_u, hu, NUSR);
    gather_emb<<<(NTXN * 32 + 255) / 256, 256>>>(x_txn,  emb_t, ht, NTXN);

    // 2) degree counts (layer-invariant) -> reciprocals
    zero_f4<<<(NTXN / 4 + 255) / 256, 256>>>((float4*)cntt, NTXN / 4);
    zero_f4<<<(NUSR / 4 + 255) / 256, 256>>>((float4*)cntu, NUSR / 4);
    count_deg<<<(NEDG + 255) / 256, 256>>>(ei0_dst, cntt, NEDG);
    count_deg<<<(NEDG + 255) / 256, 256>>>(ei1_dst, cntu, NEDG);
    make_inv<<<(NTXN + 255) / 256, 256>>>(cntt, invt, NTXN);
    make_inv<<<(NUSR + 255) / 256, 256>>>(cntu, invu, NUSR);

    // 3) layers
    for (int l = 0; l < NLAY; l++) {
        zero_f4<<<(NTXN * (HDIM / 4) + 255) / 256, 256>>>((float4*)aggt, NTXN * (HDIM / 4));
        zero_f4<<<(NUSR * (HDIM / 4) + 255) / 256, 256>>>((float4*)aggu, NUSR * (HDIM / 4));

        scatter_add<<<(NEDG * 32 + 255) / 256, 256>>>(ei0_src, ei0_dst, hu, aggt, NEDG);
        scatter_add<<<(NEDG * 32 + 255) / 256, 256>>>(ei1_src, ei1_dst, ht, aggu, NEDG);

        const size_t HH = (size_t)HDIM * HDIM;
        // txn nodes: weights/bias index (l,0), BN index (l,1)
        gemm_fused<<<(NTXN + 63) / 64, 256, GEMM_SMEM>>>(
            aggt, invt, ht,
            Wl + (size_t)(l * 2 + 0) * HH, Wr + (size_t)(l * 2 + 0) * HH,
            bl   + (size_t)(l * 2 + 0) * HDIM,
            bn_g + (size_t)(l * 2 + 1) * HDIM, bn_b + (size_t)(l * 2 + 1) * HDIM,
            bn_m + (size_t)(l * 2 + 1) * HDIM, bn_v + (size_t)(l * 2 + 1) * HDIM,
            ht, NTXN);
        // user nodes: weights/bias index (l,1), BN index (l,0)
        gemm_fused<<<(NUSR + 63) / 64, 256, GEMM_SMEM>>>(
            aggu, invu, hu,
            Wl + (size_t)(l * 2 + 1) * HH, Wr + (size_t)(l * 2 + 1) * HH,
            bl   + (size_t)(l * 2 + 1) * HDIM,
            bn_g + (size_t)(l * 2 + 0) * HDIM, bn_b + (size_t)(l * 2 + 0) * HDIM,
            bn_m + (size_t)(l * 2 + 0) * HDIM, bn_v + (size_t)(l * 2 + 0) * HDIM,
            hu, NUSR);
    }

    // 4) MLP head
    mlp_head<<<((NUSR + NTXN) * 32 + 255) / 256, 256>>>(hu, ht, W1, b1, W2, b2, out);
}

// round 10
// speedup vs baseline: 1.4256x; 1.1725x over previous
#include <cuda_runtime.h>
#include <cuda_bf16.h>
#include <cstdint>

#define NUSR 100000
#define NTXN 400000
#define NEDG 400000
#define HDIM 128
#define NLAY 3
#define HID2 64
#define OUTD 2
#define EPSV 1e-5f

// ===================== helpers =====================
__device__ __forceinline__ uint32_t smem_to_u32(const void* p) {
    uint32_t a;
    asm("{ .reg .u64 t; cvta.to.shared.u64 t, %1; cvt.u32.u64 %0, t; }" : "=r"(a) : "l"(p));
    return a;
}
// split (x,y) into bf16x2 hi and bf16x2 lo (residual)
__device__ __forceinline__ void split2(float x, float y, uint32_t& hi, uint32_t& lo) {
    __nv_bfloat162 h = __floats2bfloat162_rn(x, y);
    float rx = x - __bfloat162float(h.x);
    float ry = y - __bfloat162float(h.y);
    __nv_bfloat162 l = __floats2bfloat162_rn(rx, ry);
    hi = *(uint32_t*)&h;
    lo = *(uint32_t*)&l;
}
#define LDSM_X4(r0, r1, r2, r3, addr) \
    asm volatile("ldmatrix.sync.aligned.m8n8.x4.shared.b16 {%0,%1,%2,%3}, [%4];" \
                 : "=r"(r0), "=r"(r1), "=r"(r2), "=r"(r3) : "r"(addr))
#define MMA_BF16(d, a, b0, b1) \
    asm volatile("mma.sync.aligned.m16n8k16.row.col.f32.bf16.bf16.f32 " \
                 "{%0,%1,%2,%3}, {%4,%5,%6,%7}, {%8,%9}, {%0,%1,%2,%3};" \
                 : "+f"((d)[0]), "+f"((d)[1]), "+f"((d)[2]), "+f"((d)[3]) \
                 : "r"((a)[0]), "r"((a)[1]), "r"((a)[2]), "r"((a)[3]), "r"(b0), "r"(b1))

// ===================== scratch (device globals) =====================
__device__ float g_hu[(size_t)NUSR * HDIM];
__device__ float g_ht[(size_t)NTXN * HDIM];
__device__ float g_aggu[(size_t)NUSR * HDIM];
__device__ float g_aggt[(size_t)NTXN * HDIM];
__device__ float g_invu[NUSR];
__device__ float g_invt[NTXN];
__device__ int   g_cntu[NUSR];
__device__ int   g_cntt[NTXN];
// pre-swizzled bf16 weight images: [6 (l,t)] x (hi 64KB + lo 64KB)
__device__ float4 g_wimg[6 * 2 * 4096];

// ===================== utility kernels =====================
__global__ void zero_f4(float4* __restrict__ p, int n4) {
    int i = blockIdx.x * blockDim.x + threadIdx.x;
    if (i < n4) p[i] = make_float4(0.f, 0.f, 0.f, 0.f);
}

__global__ void gather_emb(const int* __restrict__ idx, const float* __restrict__ emb,
                           float* __restrict__ out, int n) {
    int t = blockIdx.x * blockDim.x + threadIdx.x;
    int row = t >> 5, lane = t & 31;
    if (row >= n) return;
    int src = __ldg(idx + row);
    float4 v = __ldg((const float4*)(emb + (size_t)src * HDIM) + lane);
    ((float4*)(out + (size_t)row * HDIM))[lane] = v;
}

__global__ void count_deg(const int* __restrict__ dst, int* __restrict__ cnt, int n) {
    int i = blockIdx.x * blockDim.x + threadIdx.x;
    if (i < n) atomicAdd(&cnt[__ldg(dst + i)], 1);
}

__global__ void make_inv(const int* __restrict__ cnt, float* __restrict__ inv, int n) {
    int i = blockIdx.x * blockDim.x + threadIdx.x;
    if (i < n) {
        int c = cnt[i];
        inv[i] = 1.0f / (float)(c > 1 ? c : 1);
    }
}

__global__ void scatter_add(const int* __restrict__ src, const int* __restrict__ dst,
                            const float* __restrict__ feat, float* __restrict__ agg, int n) {
    int t = blockIdx.x * blockDim.x + threadIdx.x;
    int e = t >> 5, lane = t & 31;
    if (e >= n) return;
    int s = __ldg(src + e);
    int d = __ldg(dst + e);
    float4 v = __ldg((const float4*)(feat + (size_t)s * HDIM) + lane);
    float* a = agg + (size_t)d * HDIM + lane * 4;
    asm volatile("red.global.add.v4.f32 [%0], {%1,%2,%3,%4};"
                 :: "l"(a), "f"(v.x), "f"(v.y), "f"(v.z), "f"(v.w) : "memory");
}

// ===================== weight prep =====================
// Bake Bt[n][k] = Wcat[k][n] (Wcat = [Wl; Wr], 256 k x 128 n) as bf16 hi/lo images.
// Layout: row n has 512 bytes (256 bf16 k); byte offset = n*512 + ((2k) ^ ((n&7)*16)).
// The xor makes ldmatrix's 8 row-addresses per 8x8 tile hit distinct bank groups.
__global__ void wprep(const float* __restrict__ Wl, const float* __restrict__ Wr) {
    int lt = blockIdx.x;                        // l*2+t
    const float* wl = Wl + (size_t)lt * HDIM * HDIM;
    const float* wr = Wr + (size_t)lt * HDIM * HDIM;
    unsigned char* dhi = (unsigned char*)g_wimg + (size_t)lt * 131072;
    unsigned char* dlo = dhi + 65536;
    for (int e = threadIdx.x; e < 256 * 128; e += blockDim.x) {
        int k = e >> 7, n = e & 127;
        float v = (k < 128) ? __ldg(wl + k * HDIM + n) : __ldg(wr + (k - 128) * HDIM + n);
        __nv_bfloat16 hi = __float2bfloat16_rn(v);
        __nv_bfloat16 lo = __float2bfloat16_rn(v - __bfloat162float(hi));
        uint32_t off = (uint32_t)n * 512 + (((uint32_t)k * 2) ^ (uint32_t)((n & 7) * 16));
        *(__nv_bfloat16*)(dhi + off) = hi;
        *(__nv_bfloat16*)(dlo + off) = lo;
    }
}

// ===================== tensor-core fused dual GEMM + bias + BN + ReLU =====================
// out[m,:] = relu(BN( (A1[m,:]*inv[m]) @ Wl + A2[m,:] @ Wr + bias )), in place (out == A2 ok).
// M-tile 128 rows/CTA, N=128, K=256 concat. bf16-split: D = AhWh + AlWh + AhWl (fp32 accum).
#define SMB_SCL 0
#define SMB_SFT 512
#define SMB_BHI 1024
#define SMB_BLO (1024 + 65536)
#define SMB_TOT (1024 + 131072)

__global__ __launch_bounds__(256, 1) void gemm_mma(
    const float* __restrict__ A1, const float* __restrict__ inv,
    const float* __restrict__ A2,
    const float4* __restrict__ wimg,
    const float* __restrict__ bias,
    const float* __restrict__ gma, const float* __restrict__ bta,
    const float* __restrict__ mu,  const float* __restrict__ var,
    float* __restrict__ out, int M)
{
    extern __shared__ char smem[];
    uint32_t sb = smem_to_u32(smem);
    const int tid  = threadIdx.x;
    const int lane = tid & 31;
    const int wid  = tid >> 5;

    // stage weight images (hi+lo, 128KB) linearly into smem
    {
        float4* bs = (float4*)(smem + SMB_BHI);
        #pragma unroll 4
        for (int i = tid; i < 8192; i += 256) bs[i] = __ldg(wimg + i);
    }
    // fold BN+bias constants
    if (tid < HDIM) {
        float rs = rsqrtf(__ldg(var + tid) + EPSV) * __ldg(gma + tid);
        ((float*)(smem + SMB_SCL))[tid] = rs;
        ((float*)(smem + SMB_SFT))[tid] = __ldg(bta + tid) + (__ldg(bias + tid) - __ldg(mu + tid)) * rs;
    }
    __syncthreads();

    const int warp_m = wid & 3;          // 4 m-blocks of 32 rows
    const int warp_n = wid >> 2;         // 2 n-blocks of 64 cols
    const int m0 = blockIdx.x * 128 + warp_m * 32;
    const int n0 = warp_n * 64;
    const int g  = lane >> 2;            // fragment row
    const int tg = lane & 3;             // fragment k/col pair

    // A row pointers (clamped; partial-CTA OOB rows read row M-1, stores are guarded)
    const float* pa1[4];
    const float* pa2[4];
    float iv[4];
    int rows[4] = { m0 + g, m0 + g + 8, m0 + g + 16, m0 + g + 24 };
    #pragma unroll
    for (int i = 0; i < 4; i++) {
        int r = rows[i] < M ? rows[i] : (M - 1);
        pa1[i] = A1 + (size_t)r * HDIM;
        pa2[i] = A2 + (size_t)r * HDIM;
        iv[i]  = __ldg(inv + r);
    }

    // ldmatrix per-thread address components
    const int n_off  = (lane & 7) + ((lane >> 4) << 3);  // row within 16-n group
    const int k_half = (lane & 8) << 1;                  // 0 or 16 bytes (k 0-7 vs 8-15)
    const uint32_t xorv = (uint32_t)((n_off & 7) << 4);
    uint32_t brow_hi[4], brow_lo[4];
    #pragma unroll
    for (int np = 0; np < 4; np++) {
        uint32_t nrow = (uint32_t)(n0 + np * 16 + n_off) * 512u;
        brow_hi[np] = sb + SMB_BHI + nrow;
        brow_lo[np] = sb + SMB_BLO + nrow;
    }

    float acc[2][8][4];
    #pragma unroll
    for (int mt = 0; mt < 2; mt++)
        #pragma unroll
        for (int nt = 0; nt < 8; nt++)
            #pragma unroll
            for (int q = 0; q < 4; q++) acc[mt][nt][q] = 0.f;

    #pragma unroll 2
    for (int kk = 0; kk < 16; kk++) {
        // ---- A fragments: load 4 rows x 2 k-pairs from global, split hi/lo ----
        float2 x[4][2];
        if (kk < 8) {
            int k0 = kk * 16 + tg * 2;
            #pragma unroll
            for (int i = 0; i < 4; i++) {
                float2 v0 = *(const float2*)(pa1[i] + k0);
                float2 v1 = *(const float2*)(pa1[i] + k0 + 8);
                v0.x *= iv[i]; v0.y *= iv[i]; v1.x *= iv[i]; v1.y *= iv[i];
                x[i][0] = v0; x[i][1] = v1;
            }
        } else {
            int k0 = (kk - 8) * 16 + tg * 2;
            #pragma unroll
            for (int i = 0; i < 4; i++) {
                x[i][0] = *(const float2*)(pa2[i] + k0);
                x[i][1] = *(const float2*)(pa2[i] + k0 + 8);
            }
        }
        uint32_t ah[2][4], al[2][4];
        #pragma unroll
        for (int mt = 0; mt < 2; mt++) {
            int i0 = mt * 2, i1 = mt * 2 + 1;
            split2(x[i0][0].x, x[i0][0].y, ah[mt][0], al[mt][0]);
            split2(x[i1][0].x, x[i1][0].y, ah[mt][1], al[mt][1]);
            split2(x[i0][1].x, x[i0][1].y, ah[mt][2], al[mt][2]);
            split2(x[i1][1].x, x[i1][1].y, ah[mt][3], al[mt][3]);
        }

        // ---- B fragments (ldmatrix) + 3-chain mma ----
        uint32_t kterm = (uint32_t)((kk * 32 + k_half)) ^ xorv;
        #pragma unroll
        for (int np = 0; np < 4; np++) {
            uint32_t bh0, bh1, bh2, bh3, bl0, bl1, bl2, bl3;
            LDSM_X4(bh0, bh1, bh2, bh3, brow_hi[np] + kterm);
            LDSM_X4(bl0, bl1, bl2, bl3, brow_lo[np] + kterm);
            #pragma unroll
            for (int mt = 0; mt < 2; mt++) {
                MMA_BF16(acc[mt][2 * np],     ah[mt], bh0, bh1);
                MMA_BF16(acc[mt][2 * np],     al[mt], bh0, bh1);
                MMA_BF16(acc[mt][2 * np],     ah[mt], bl0, bl1);
                MMA_BF16(acc[mt][2 * np + 1], ah[mt], bh2, bh3);
                MMA_BF16(acc[mt][2 * np + 1], al[mt], bh2, bh3);
                MMA_BF16(acc[mt][2 * np + 1], ah[mt], bl2, bl3);
            }
        }
    }

    // all in-place input reads complete before any stores (partial-CTA clamp aliasing)
    __syncthreads();

    // ---- epilogue: y = relu(acc*scl + sft) ----
    const float* scl = (const float*)(smem + SMB_SCL);
    const float* sft = (const float*)(smem + SMB_SFT);
    #pragma unroll
    for (int mt = 0; mt < 2; mt++) {
        int r_lo = m0 + mt * 16 + g;
        int r_hi = r_lo + 8;
        #pragma unroll
        for (int nt = 0; nt < 8; nt++) {
            int c = n0 + nt * 8 + tg * 2;
            float s0 = scl[c], s1 = scl[c + 1];
            float f0 = sft[c], f1 = sft[c + 1];
            if (r_lo < M) {
                float2 o;
                o.x = fmaxf(fmaf(acc[mt][nt][0], s0, f0), 0.f);
                o.y = fmaxf(fmaf(acc[mt][nt][1], s1, f1), 0.f);
                *(float2*)(out + (size_t)r_lo * HDIM + c) = o;
            }
            if (r_hi < M) {
                float2 o;
                o.x = fmaxf(fmaf(acc[mt][nt][2], s0, f0), 0.f);
                o.y = fmaxf(fmaf(acc[mt][nt][3], s1, f1), 0.f);
                *(float2*)(out + (size_t)r_hi * HDIM + c) = o;
            }
        }
    }
}

// ===================== fused MLP head =====================
__global__ __launch_bounds__(256) void mlp_head(
    const float* __restrict__ hu, const float* __restrict__ ht,
    const float* __restrict__ W1, const float* __restrict__ b1,
    const float* __restrict__ W2, const float* __restrict__ b2,
    float* __restrict__ out)
{
    __shared__ float sW1[HDIM * HID2];
    __shared__ float sb1[HID2];
    __shared__ float sW2[HID2 * OUTD];
    for (int i = threadIdx.x; i < HDIM * HID2; i += 256) sW1[i] = W1[i];
    if (threadIdx.x < HID2) sb1[threadIdx.x] = b1[threadIdx.x];
    if (threadIdx.x < HID2 * OUTD) sW2[threadIdx.x] = W2[threadIdx.x];
    __syncthreads();

    int gw   = (blockIdx.x * 256 + threadIdx.x) >> 5;
    int lane = threadIdx.x & 31;
    if (gw >= NUSR + NTXN) return;

    const float* hrow = (gw < NUSR) ? hu + (size_t)gw * HDIM
                                    : ht + (size_t)(gw - NUSR) * HDIM;
    float4 hv = __ldg((const float4*)hrow + lane);
    float hb[4] = {hv.x, hv.y, hv.z, hv.w};

    float acc0 = 0.f, acc1 = 0.f;
    #pragma unroll
    for (int j = 0; j < 4; j++) {
        #pragma unroll
        for (int kk = 0; kk < 32; kk++) {
            float hk = __shfl_sync(0xffffffffu, hb[j], kk);
            int k = kk * 4 + j;
            acc0 = fmaf(hk, sW1[k * HID2 + lane],      acc0);
            acc1 = fmaf(hk, sW1[k * HID2 + lane + 32], acc1);
        }
    }
    float h0 = fmaxf(acc0 + sb1[lane],      0.f);
    float h1 = fmaxf(acc1 + sb1[lane + 32], 0.f);
    float o0 = h0 * sW2[lane * OUTD + 0] + h1 * sW2[(lane + 32) * OUTD + 0];
    float o1 = h0 * sW2[lane * OUTD + 1] + h1 * sW2[(lane + 32) * OUTD + 1];
    #pragma unroll
    for (int off = 16; off > 0; off >>= 1) {
        o0 += __shfl_down_sync(0xffffffffu, o0, off);
        o1 += __shfl_down_sync(0xffffffffu, o1, off);
    }
    if (lane == 0) {
        out[(size_t)gw * OUTD + 0] = o0 + __ldg(b2 + 0);
        out[(size_t)gw * OUTD + 1] = o1 + __ldg(b2 + 1);
    }
}

// ===================== launcher =====================
extern "C" void kernel_launch(void* const* d_in, const int* in_sizes, int n_in,
                              void* d_out, int out_size) {
    (void)in_sizes; (void)n_in; (void)out_size;
    const int*   x_user  = (const int*)  d_in[0];
    const int*   x_txn   = (const int*)  d_in[1];
    const int*   ei0_src = (const int*)  d_in[2];
    const int*   ei0_dst = (const int*)  d_in[3];
    const int*   ei1_src = (const int*)  d_in[4];
    const int*   ei1_dst = (const int*)  d_in[5];
    const float* emb_u   = (const float*)d_in[6];
    const float* emb_t   = (const float*)d_in[7];
    const float* Wl      = (const float*)d_in[8];
    const float* bl      = (const float*)d_in[9];
    const float* Wr      = (const float*)d_in[10];
    const float* bn_g    = (const float*)d_in[11];
    const float* bn_b    = (const float*)d_in[12];
    const float* bn_m    = (const float*)d_in[13];
    const float* bn_v    = (const float*)d_in[14];
    const float* W1      = (const float*)d_in[15];
    const float* b1      = (const float*)d_in[16];
    const float* W2      = (const float*)d_in[17];
    const float* b2      = (const float*)d_in[18];
    float* out = (float*)d_out;

    float *hu, *ht, *aggu, *aggt, *invu, *invt;
    int *cntu, *cntt;
    float4* wimg;
    cudaGetSymbolAddress((void**)&hu,   g_hu);
    cudaGetSymbolAddress((void**)&ht,   g_ht);
    cudaGetSymbolAddress((void**)&aggu, g_aggu);
    cudaGetSymbolAddress((void**)&aggt, g_aggt);
    cudaGetSymbolAddress((void**)&invu, g_invu);
    cudaGetSymbolAddress((void**)&invt, g_invt);
    cudaGetSymbolAddress((void**)&cntu, g_cntu);
    cudaGetSymbolAddress((void**)&cntt, g_cntt);
    cudaGetSymbolAddress((void**)&wimg, g_wimg);

    cudaFuncSetAttribute(gemm_mma, cudaFuncAttributeMaxDynamicSharedMemorySize, SMB_TOT);

    // 0) bake weight images (hi/lo bf16, ldmatrix-swizzled)
    wprep<<<6, 256>>>(Wl, Wr);

    // 1) embedding gather
    gather_emb<<<(NUSR * 32 + 255) / 256, 256>>>(x_user, emb_u, hu, NUSR);
    gather_emb<<<(NTXN * 32 + 255) / 256, 256>>>(x_txn,  emb_t, ht, NTXN);

    // 2) degree counts (layer-invariant) -> reciprocals
    zero_f4<<<(NTXN / 4 + 255) / 256, 256>>>((float4*)cntt, NTXN / 4);
    zero_f4<<<(NUSR / 4 + 255) / 256, 256>>>((float4*)cntu, NUSR / 4);
    count_deg<<<(NEDG + 255) / 256, 256>>>(ei0_dst, cntt, NEDG);
    count_deg<<<(NEDG + 255) / 256, 256>>>(ei1_dst, cntu, NEDG);
    make_inv<<<(NTXN + 255) / 256, 256>>>(cntt, invt, NTXN);
    make_inv<<<(NUSR + 255) / 256, 256>>>(cntu, invu, NUSR);

    // 3) layers
    for (int l = 0; l < NLAY; l++) {
        zero_f4<<<(NTXN * (HDIM / 4) + 255) / 256, 256>>>((float4*)aggt, NTXN * (HDIM / 4));
        zero_f4<<<(NUSR * (HDIM / 4) + 255) / 256, 256>>>((float4*)aggu, NUSR * (HDIM / 4));

        scatter_add<<<(NEDG * 32 + 255) / 256, 256>>>(ei0_src, ei0_dst, hu, aggt, NEDG);
        scatter_add<<<(NEDG * 32 + 255) / 256, 256>>>(ei1_src, ei1_dst, ht, aggu, NEDG);

        // txn nodes: weights/bias (l,0), BN (l,1)
        {
            int lt = l * 2 + 0;
            gemm_mma<<<(NTXN + 127) / 128, 256, SMB_TOT>>>(
                aggt, invt, ht,
                wimg + (size_t)lt * 8192,
                bl   + (size_t)lt * HDIM,
                bn_g + (size_t)(l * 2 + 1) * HDIM, bn_b + (size_t)(l * 2 + 1) * HDIM,
                bn_m + (size_t)(l * 2 + 1) * HDIM, bn_v + (size_t)(l * 2 + 1) * HDIM,
                ht, NTXN);
        }
        // user nodes: weights/bias (l,1), BN (l,0)
        {
            int lt = l * 2 + 1;
            gemm_mma<<<(NUSR + 127) / 128, 256, SMB_TOT>>>(
                aggu, invu, hu,
                wimg + (size_t)lt * 8192,
                bl   + (size_t)lt * HDIM,
                bn_g + (size_t)(l * 2 + 0) * HDIM, bn_b + (size_t)(l * 2 + 0) * HDIM,
                bn_m + (size_t)(l * 2 + 0) * HDIM, bn_v + (size_t)(l * 2 + 0) * HDIM,
                hu, NUSR);
        }
    }

    // 4) MLP head
    mlp_head<<<((NUSR + NTXN) * 32 + 255) / 256, 256>>>(hu, ht, W1, b1, W2, b2, out);
}

// round 11
// speedup vs baseline: 2.0320x; 1.4254x over previous
#include <cuda_runtime.h>
#include <cuda_bf16.h>
#include <cstdint>

#define NUSR 100000
#define NTXN 400000
#define NEDG 400000
#define HDIM 128
#define NLAY 3
#define HID2 64
#define OUTD 2
#define EPSV 1e-5f
#define NTOT (NUSR + NTXN)

// ===================== helpers =====================
__device__ __forceinline__ uint32_t smem_to_u32(const void* p) {
    uint32_t a;
    asm("{ .reg .u64 t; cvta.to.shared.u64 t, %1; cvt.u32.u64 %0, t; }" : "=r"(a) : "l"(p));
    return a;
}
__device__ __forceinline__ void split2(float x, float y, uint32_t& hi, uint32_t& lo) {
    __nv_bfloat162 h = __floats2bfloat162_rn(x, y);
    float rx = x - __bfloat162float(h.x);
    float ry = y - __bfloat162float(h.y);
    __nv_bfloat162 l = __floats2bfloat162_rn(rx, ry);
    hi = *(uint32_t*)&h;
    lo = *(uint32_t*)&l;
}
#define LDSM_X4(r0, r1, r2, r3, addr) \
    asm volatile("ldmatrix.sync.aligned.m8n8.x4.shared.b16 {%0,%1,%2,%3}, [%4];" \
                 : "=r"(r0), "=r"(r1), "=r"(r2), "=r"(r3) : "r"(addr))
#define MMA_BF16(d, a, b0, b1) \
    asm volatile("mma.sync.aligned.m16n8k16.row.col.f32.bf16.bf16.f32 " \
                 "{%0,%1,%2,%3}, {%4,%5,%6,%7}, {%8,%9}, {%0,%1,%2,%3};" \
                 : "+f"((d)[0]), "+f"((d)[1]), "+f"((d)[2]), "+f"((d)[3]) \
                 : "r"((a)[0]), "r"((a)[1]), "r"((a)[2]), "r"((a)[3]), "r"(b0), "r"(b1))

// ===================== scratch (device globals) =====================
__device__ float g_hu[(size_t)NUSR * HDIM];
__device__ float g_ht[(size_t)NTXN * HDIM];
__device__ float g_aggu[(size_t)NUSR * HDIM];
__device__ float g_aggt[(size_t)NTXN * HDIM];
__device__ int   g_cntu[NUSR];
__device__ int   g_cntt[NTXN];
__device__ int   g_startu[NUSR];
__device__ int   g_startt[NTXN];
__device__ int   g_tmpu[NUSR];
__device__ int   g_tmpt[NTXN];
__device__ int   g_permu[NEDG];
__device__ int   g_permt[NEDG];
__device__ int   g_cursor[2];
// pre-swizzled bf16 weight images: [6 (l,t)] x (hi 64KB + lo 64KB)
__device__ float4 g_wimg[6 * 2 * 4096];
// W1 image: hi 16KB + lo 16KB
__device__ float4 g_w1img[2048];

// ===================== utility kernels =====================
__global__ void zero_i(int* __restrict__ p, int n) {
    int i = blockIdx.x * blockDim.x + threadIdx.x;
    if (i < n) p[i] = 0;
}

__global__ void gather_emb(const int* __restrict__ idx, const float* __restrict__ emb,
                           float* __restrict__ out, int n) {
    int t = blockIdx.x * blockDim.x + threadIdx.x;
    int row = t >> 5, lane = t & 31;
    if (row >= n) return;
    int src = __ldg(idx + row);
    float4 v = __ldg((const float4*)(emb + (size_t)src * HDIM) + lane);
    ((float4*)(out + (size_t)row * HDIM))[lane] = v;
}

__global__ void count_deg(const int* __restrict__ dst, int* __restrict__ cnt, int n) {
    int i = blockIdx.x * blockDim.x + threadIdx.x;
    if (i < n) atomicAdd(&cnt[__ldg(dst + i)], 1);
}

// block-aggregated offset assignment: start[i] = running sum of cnt (any order), tmp copy
__global__ void assign_off(const int* __restrict__ cnt, int* __restrict__ start,
                           int* __restrict__ tmp, int* cursor, int n) {
    __shared__ int wsum[8];
    __shared__ int sbase;
    int i = blockIdx.x * 256 + threadIdx.x;
    int lane = threadIdx.x & 31, w = threadIdx.x >> 5;
    int c = (i < n) ? __ldg(cnt + i) : 0;
    int pre = c;
    #pragma unroll
    for (int o = 1; o < 32; o <<= 1) {
        int u = __shfl_up_sync(0xffffffffu, pre, o);
        if (lane >= o) pre += u;
    }
    if (lane == 31) wsum[w] = pre;
    __syncthreads();
    if (threadIdx.x == 0) {
        int s = 0;
        #pragma unroll
        for (int j = 0; j < 8; j++) { int t = wsum[j]; wsum[j] = s; s += t; }
        sbase = atomicAdd(cursor, s);
    }
    __syncthreads();
    int off = sbase + wsum[w] + pre - c;
    if (i < n) { start[i] = off; tmp[i] = off; }
}

__global__ void fill_perm(const int* __restrict__ src, const int* __restrict__ dst,
                          int* __restrict__ tmp, int* __restrict__ perm, int n) {
    int i = blockIdx.x * blockDim.x + threadIdx.x;
    if (i < n) {
        int d = __ldg(dst + i);
        int slot = atomicAdd(&tmp[d], 1);
        perm[slot] = __ldg(src + i);
    }
}

// warp per dst node: agg[d,:] = mean over CSR neighbors of feat[src,:]
__global__ void agg_mean(const int* __restrict__ start, const int* __restrict__ cnt,
                         const int* __restrict__ perm, const float* __restrict__ feat,
                         float* __restrict__ agg, int n) {
    int t = blockIdx.x * blockDim.x + threadIdx.x;
    int d = t >> 5, lane = t & 31;
    if (d >= n) return;
    int s = __ldg(start + d), c = __ldg(cnt + d);
    float4 acc = make_float4(0.f, 0.f, 0.f, 0.f);
    for (int j = 0; j < c; j++) {
        int src = __ldg(perm + s + j);
        float4 v = __ldg((const float4*)(feat + (size_t)src * HDIM) + lane);
        acc.x += v.x; acc.y += v.y; acc.z += v.z; acc.w += v.w;
    }
    float sc = 1.f / (float)(c > 1 ? c : 1);
    acc.x *= sc; acc.y *= sc; acc.z *= sc; acc.w *= sc;
    ((float4*)(agg + (size_t)d * HDIM))[lane] = acc;
}

// ===================== weight prep =====================
// Bt[n][k] = Wcat[k][n] (Wcat = [Wl; Wr], 256 k x 128 n), bf16 hi/lo, row = 512B,
// byte offset = n*512 + ((2k) ^ ((n&7)*16))  (xor makes ldmatrix conflict-free)
__global__ void wprep(const float* __restrict__ Wl, const float* __restrict__ Wr) {
    int lt = blockIdx.x;
    const float* wl = Wl + (size_t)lt * HDIM * HDIM;
    const float* wr = Wr + (size_t)lt * HDIM * HDIM;
    unsigned char* dhi = (unsigned char*)g_wimg + (size_t)lt * 131072;
    unsigned char* dlo = dhi + 65536;
    for (int e = threadIdx.x; e < 256 * 128; e += blockDim.x) {
        int k = e >> 7, n = e & 127;
        float v = (k < 128) ? __ldg(wl + k * HDIM + n) : __ldg(wr + (k - 128) * HDIM + n);
        __nv_bfloat16 hi = __float2bfloat16_rn(v);
        __nv_bfloat16 lo = __float2bfloat16_rn(v - __bfloat162float(hi));
        uint32_t off = (uint32_t)n * 512 + (((uint32_t)k * 2) ^ (uint32_t)((n & 7) * 16));
        *(__nv_bfloat16*)(dhi + off) = hi;
        *(__nv_bfloat16*)(dlo + off) = lo;
    }
}
// W1t[n][k] = W1[k][n] (128 k x 64 n), row = 256B, offset = n*256 + ((2k)^((n&7)*16))
__global__ void w1prep(const float* __restrict__ W1) {
    unsigned char* dhi = (unsigned char*)g_w1img;
    unsigned char* dlo = dhi + 16384;
    for (int e = blockIdx.x * blockDim.x + threadIdx.x; e < 128 * 64; e += gridDim.x * blockDim.x) {
        int k = e >> 6, n = e & 63;
        float v = __ldg(W1 + k * HID2 + n);
        __nv_bfloat16 hi = __float2bfloat16_rn(v);
        __nv_bfloat16 lo = __float2bfloat16_rn(v - __bfloat162float(hi));
        uint32_t off = (uint32_t)n * 256 + (((uint32_t)k * 2) ^ (uint32_t)((n & 7) * 16));
        *(__nv_bfloat16*)(dhi + off) = hi;
        *(__nv_bfloat16*)(dlo + off) = lo;
    }
}

// ===================== tensor-core fused dual GEMM + bias + BN + ReLU =====================
// out[m,:] = relu(BN( A1[m,:] @ Wl + A2[m,:] @ Wr + bias )), in place (out == A2 ok).
// M-tile 128 rows/CTA, N=128, K=256 concat. bf16-split: D = AhWh + AlWh + AhWl.
#define SMB_SCL 0
#define SMB_SFT 512
#define SMB_BHI 1024
#define SMB_BLO (1024 + 65536)
#define SMB_TOT (1024 + 131072)

__global__ __launch_bounds__(256, 1) void gemm_mma(
    const float* __restrict__ A1, const float* __restrict__ A2,
    const float4* __restrict__ wimg,
    const float* __restrict__ bias,
    const float* __restrict__ gma, const float* __restrict__ bta,
    const float* __restrict__ mu,  const float* __restrict__ var,
    float* __restrict__ out, int M)
{
    extern __shared__ char smem[];
    uint32_t sb = smem_to_u32(smem);
    const int tid  = threadIdx.x;
    const int lane = tid & 31;
    const int wid  = tid >> 5;

    {
        float4* bs = (float4*)(smem + SMB_BHI);
        #pragma unroll 4
        for (int i = tid; i < 8192; i += 256) bs[i] = __ldg(wimg + i);
    }
    if (tid < HDIM) {
        float rs = rsqrtf(__ldg(var + tid) + EPSV) * __ldg(gma + tid);
        ((float*)(smem + SMB_SCL))[tid] = rs;
        ((float*)(smem + SMB_SFT))[tid] = __ldg(bta + tid) + (__ldg(bias + tid) - __ldg(mu + tid)) * rs;
    }
    __syncthreads();

    const int warp_m = wid & 3;
    const int warp_n = wid >> 2;
    const int m0 = blockIdx.x * 128 + warp_m * 32;
    const int n0 = warp_n * 64;
    const int g  = lane >> 2;
    const int tg = lane & 3;

    const float* pa1[4];
    const float* pa2[4];
    int rows[4] = { m0 + g, m0 + g + 8, m0 + g + 16, m0 + g + 24 };
    #pragma unroll
    for (int i = 0; i < 4; i++) {
        int r = rows[i] < M ? rows[i] : (M - 1);
        pa1[i] = A1 + (size_t)r * HDIM;
        pa2[i] = A2 + (size_t)r * HDIM;
    }

    const int n_off  = (lane & 7) + ((lane >> 4) << 3);
    const int k_half = (lane & 8) << 1;
    const uint32_t xorv = (uint32_t)((n_off & 7) << 4);
    uint32_t brow_hi[4], brow_lo[4];
    #pragma unroll
    for (int np = 0; np < 4; np++) {
        uint32_t nrow = (uint32_t)(n0 + np * 16 + n_off) * 512u;
        brow_hi[np] = sb + SMB_BHI + nrow;
        brow_lo[np] = sb + SMB_BLO + nrow;
    }

    float acc[2][8][4];
    #pragma unroll
    for (int mt = 0; mt < 2; mt++)
        #pragma unroll
        for (int nt = 0; nt < 8; nt++)
            #pragma unroll
            for (int q = 0; q < 4; q++) acc[mt][nt][q] = 0.f;

    #pragma unroll 2
    for (int kk = 0; kk < 16; kk++) {
        float2 x[4][2];
        if (kk < 8) {
            int k0 = kk * 16 + tg * 2;
            #pragma unroll
            for (int i = 0; i < 4; i++) {
                x[i][0] = *(const float2*)(pa1[i] + k0);
                x[i][1] = *(const float2*)(pa1[i] + k0 + 8);
            }
        } else {
            int k0 = (kk - 8) * 16 + tg * 2;
            #pragma unroll
            for (int i = 0; i < 4; i++) {
                x[i][0] = *(const float2*)(pa2[i] + k0);
                x[i][1] = *(const float2*)(pa2[i] + k0 + 8);
            }
        }
        uint32_t ah[2][4], al[2][4];
        #pragma unroll
        for (int mt = 0; mt < 2; mt++) {
            int i0 = mt * 2, i1 = mt * 2 + 1;
            split2(x[i0][0].x, x[i0][0].y, ah[mt][0], al[mt][0]);
            split2(x[i1][0].x, x[i1][0].y, ah[mt][1], al[mt][1]);
            split2(x[i0][1].x, x[i0][1].y, ah[mt][2], al[mt][2]);
            split2(x[i1][1].x, x[i1][1].y, ah[mt][3], al[mt][3]);
        }

        uint32_t kterm = (uint32_t)((kk * 32 + k_half)) ^ xorv;
        #pragma unroll
        for (int np = 0; np < 4; np++) {
            uint32_t bh0, bh1, bh2, bh3, bl0, bl1, bl2, bl3;
            LDSM_X4(bh0, bh1, bh2, bh3, brow_hi[np] + kterm);
            LDSM_X4(bl0, bl1, bl2, bl3, brow_lo[np] + kterm);
            #pragma unroll
            for (int mt = 0; mt < 2; mt++) {
                MMA_BF16(acc[mt][2 * np],     ah[mt], bh0, bh1);
                MMA_BF16(acc[mt][2 * np],     al[mt], bh0, bh1);
                MMA_BF16(acc[mt][2 * np],     ah[mt], bl0, bl1);
                MMA_BF16(acc[mt][2 * np + 1], ah[mt], bh2, bh3);
                MMA_BF16(acc[mt][2 * np + 1], al[mt], bh2, bh3);
                MMA_BF16(acc[mt][2 * np + 1], ah[mt], bl2, bl3);
            }
        }
    }

    __syncthreads();   // all in-place reads done before stores (clamp aliasing)

    const float* scl = (const float*)(smem + SMB_SCL);
    const float* sft = (const float*)(smem + SMB_SFT);
    #pragma unroll
    for (int mt = 0; mt < 2; mt++) {
        int r_lo = m0 + mt * 16 + g;
        int r_hi = r_lo + 8;
        #pragma unroll
        for (int nt = 0; nt < 8; nt++) {
            int c = n0 + nt * 8 + tg * 2;
            float s0 = scl[c], s1 = scl[c + 1];
            float f0 = sft[c], f1 = sft[c + 1];
            if (r_lo < M) {
                float2 o;
                o.x = fmaxf(fmaf(acc[mt][nt][0], s0, f0), 0.f);
                o.y = fmaxf(fmaf(acc[mt][nt][1], s1, f1), 0.f);
                *(float2*)(out + (size_t)r_lo * HDIM + c) = o;
            }
            if (r_hi < M) {
                float2 o;
                o.x = fmaxf(fmaf(acc[mt][nt][2], s0, f0), 0.f);
                o.y = fmaxf(fmaf(acc[mt][nt][3], s1, f1), 0.f);
                *(float2*)(out + (size_t)r_hi * HDIM + c) = o;
            }
        }
    }
}

// ===================== tensor-core MLP head =====================
// out[r,:] = relu(h[r,:] @ W1 + b1) @ W2 + b2 ; h = concat(hu, ht) rows.
// CTA = 256 thr / 8 warps; warp = 32 rows x 64 cols; 256 rows/CTA. bf16-split 3-chain.
__global__ __launch_bounds__(256, 2) void mlp_mma(
    const float* __restrict__ hu, const float* __restrict__ ht,
    const float4* __restrict__ w1img,
    const float* __restrict__ b1, const float* __restrict__ W2, const float* __restrict__ b2,
    float* __restrict__ out)
{
    __shared__ float4 sB[2048];     // 32 KB: hi 16KB + lo 16KB
    __shared__ float sb1[HID2];
    __shared__ float sW2[HID2 * OUTD];
    __shared__ float sb2[OUTD];
    for (int i = threadIdx.x; i < 2048; i += 256) sB[i] = __ldg(w1img + i);
    if (threadIdx.x < HID2) sb1[threadIdx.x] = __ldg(b1 + threadIdx.x);
    if (threadIdx.x < HID2 * OUTD) sW2[threadIdx.x] = __ldg(W2 + threadIdx.x);
    if (threadIdx.x < OUTD) sb2[threadIdx.x] = __ldg(b2 + threadIdx.x);
    __syncthreads();

    const int lane = threadIdx.x & 31;
    const int wid  = threadIdx.x >> 5;
    const int m0 = blockIdx.x * 256 + wid * 32;
    const int g  = lane >> 2;
    const int tg = lane & 3;

    const float* pa[4];
    int rows[4] = { m0 + g, m0 + g + 8, m0 + g + 16, m0 + g + 24 };
    #pragma unroll
    for (int i = 0; i < 4; i++) {
        int r = rows[i] < NTOT ? rows[i] : (NTOT - 1);
        pa[i] = (r < NUSR) ? hu + (size_t)r * HDIM : ht + (size_t)(r - NUSR) * HDIM;
    }

    const int n_off  = (lane & 7) + ((lane >> 4) << 3);
    const int k_half = (lane & 8) << 1;
    const uint32_t xorv = (uint32_t)((n_off & 7) << 4);
    uint32_t sbu = smem_to_u32(sB);
    uint32_t brow_hi[4], brow_lo[4];
    #pragma unroll
    for (int np = 0; np < 4; np++) {
        uint32_t nrow = (uint32_t)(np * 16 + n_off) * 256u;
        brow_hi[np] = sbu + nrow;
        brow_lo[np] = sbu + 16384u + nrow;
    }

    float acc[2][8][4];
    #pragma unroll
    for (int mt = 0; mt < 2; mt++)
        #pragma unroll
        for (int nt = 0; nt < 8; nt++)
            #pragma unroll
            for (int q = 0; q < 4; q++) acc[mt][nt][q] = 0.f;

    #pragma unroll 2
    for (int kk = 0; kk < 8; kk++) {
        int k0 = kk * 16 + tg * 2;
        float2 x[4][2];
        #pragma unroll
        for (int i = 0; i < 4; i++) {
            x[i][0] = *(const float2*)(pa[i] + k0);
            x[i][1] = *(const float2*)(pa[i] + k0 + 8);
        }
        uint32_t ah[2][4], al[2][4];
        #pragma unroll
        for (int mt = 0; mt < 2; mt++) {
            int i0 = mt * 2, i1 = mt * 2 + 1;
            split2(x[i0][0].x, x[i0][0].y, ah[mt][0], al[mt][0]);
            split2(x[i1][0].x, x[i1][0].y, ah[mt][1], al[mt][1]);
            split2(x[i0][1].x, x[i0][1].y, ah[mt][2], al[mt][2]);
            split2(x[i1][1].x, x[i1][1].y, ah[mt][3], al[mt][3]);
        }
        uint32_t kterm = (uint32_t)((kk * 32 + k_half)) ^ xorv;
        #pragma unroll
        for (int np = 0; np < 4; np++) {
            uint32_t bh0, bh1, bh2, bh3, bl0, bl1, bl2, bl3;
            LDSM_X4(bh0, bh1, bh2, bh3, brow_hi[np] + kterm);
            LDSM_X4(bl0, bl1, bl2, bl3, brow_lo[np] + kterm);
            #pragma unroll
            for (int mt = 0; mt < 2; mt++) {
                MMA_BF16(acc[mt][2 * np],     ah[mt], bh0, bh1);
                MMA_BF16(acc[mt][2 * np],     al[mt], bh0, bh1);
                MMA_BF16(acc[mt][2 * np],     ah[mt], bl0, bl1);
                MMA_BF16(acc[mt][2 * np + 1], ah[mt], bh2, bh3);
                MMA_BF16(acc[mt][2 * np + 1], al[mt], bh2, bh3);
                MMA_BF16(acc[mt][2 * np + 1], ah[mt], bl2, bl3);
            }
        }
    }

    // epilogue: hidden = relu(acc + b1); out = hidden @ W2 + b2 (quad reduce over cols)
    #pragma unroll
    for (int mt = 0; mt < 2; mt++) {
        #pragma unroll
        for (int half = 0; half < 2; half++) {      // half 0: rows g, half 1: rows g+8
            int row = m0 + mt * 16 + g + half * 8;
            float oA = 0.f, oB = 0.f;
            #pragma unroll
            for (int nt = 0; nt < 8; nt++) {
                int c = nt * 8 + tg * 2;
                float h0 = fmaxf(acc[mt][nt][half * 2 + 0] + sb1[c],     0.f);
                float h1 = fmaxf(acc[mt][nt][half * 2 + 1] + sb1[c + 1], 0.f);
                oA = fmaf(h0, sW2[c * OUTD],           fmaf(h1, sW2[(c + 1) * OUTD],     oA));
                oB = fmaf(h0, sW2[c * OUTD + 1],       fmaf(h1, sW2[(c + 1) * OUTD + 1], oB));
            }
            oA += __shfl_xor_sync(0xffffffffu, oA, 1);
            oA += __shfl_xor_sync(0xffffffffu, oA, 2);
            oB += __shfl_xor_sync(0xffffffffu, oB, 1);
            oB += __shfl_xor_sync(0xffffffffu, oB, 2);
            if (tg == 0 && row < NTOT) {
                out[(size_t)row * OUTD + 0] = oA + sb2[0];
                out[(size_t)row * OUTD + 1] = oB + sb2[1];
            }
        }
    }
}

// ===================== launcher =====================
extern "C" void kernel_launch(void* const* d_in, const int* in_sizes, int n_in,
                              void* d_out, int out_size) {
    (void)in_sizes; (void)n_in; (void)out_size;
    const int*   x_user  = (const int*)  d_in[0];
    const int*   x_txn   = (const int*)  d_in[1];
    const int*   ei0_src = (const int*)  d_in[2];
    const int*   ei0_dst = (const int*)  d_in[3];
    const int*   ei1_src = (const int*)  d_in[4];
    const int*   ei1_dst = (const int*)  d_in[5];
    const float* emb_u   = (const float*)d_in[6];
    const float* emb_t   = (const float*)d_in[7];
    const float* Wl      = (const float*)d_in[8];
    const float* bl      = (const float*)d_in[9];
    const float* Wr      = (const float*)d_in[10];
    const float* bn_g    = (const float*)d_in[11];
    const float* bn_b    = (const float*)d_in[12];
    const float* bn_m    = (const float*)d_in[13];
    const float* bn_v    = (const float*)d_in[14];
    const float* W1      = (const float*)d_in[15];
    const float* b1      = (const float*)d_in[16];
    const float* W2      = (const float*)d_in[17];
    const float* b2      = (const float*)d_in[18];
    float* out = (float*)d_out;

    float *hu, *ht, *aggu, *aggt;
    int *cntu, *cntt, *startu, *startt, *tmpu, *tmpt, *permu, *permt, *cursor;
    float4 *wimg, *w1img;
    cudaGetSymbolAddress((void**)&hu,     g_hu);
    cudaGetSymbolAddress((void**)&ht,     g_ht);
    cudaGetSymbolAddress((void**)&aggu,   g_aggu);
    cudaGetSymbolAddress((void**)&aggt,   g_aggt);
    cudaGetSymbolAddress((void**)&cntu,   g_cntu);
    cudaGetSymbolAddress((void**)&cntt,   g_cntt);
    cudaGetSymbolAddress((void**)&startu, g_startu);
    cudaGetSymbolAddress((void**)&startt, g_startt);
    cudaGetSymbolAddress((void**)&tmpu,   g_tmpu);
    cudaGetSymbolAddress((void**)&tmpt,   g_tmpt);
    cudaGetSymbolAddress((void**)&permu,  g_permu);
    cudaGetSymbolAddress((void**)&permt,  g_permt);
    cudaGetSymbolAddress((void**)&cursor, g_cursor);
    cudaGetSymbolAddress((void**)&wimg,   g_wimg);
    cudaGetSymbolAddress((void**)&w1img,  g_w1img);

    cudaFuncSetAttribute(gemm_mma, cudaFuncAttributeMaxDynamicSharedMemorySize, SMB_TOT);

    // 0) bake weight images
    wprep<<<6, 256>>>(Wl, Wr);
    w1prep<<<8, 256>>>(W1);

    // 1) embedding gather
    gather_emb<<<(NUSR * 32 + 255) / 256, 256>>>(x_user, emb_u, hu, NUSR);
    gather_emb<<<(NTXN * 32 + 255) / 256, 256>>>(x_txn,  emb_t, ht, NTXN);

    // 2) CSR build (layer-invariant): counts -> offsets -> permutation
    zero_i<<<(NTXN + 255) / 256, 256>>>(cntt, NTXN);
    zero_i<<<(NUSR + 255) / 256, 256>>>(cntu, NUSR);
    zero_i<<<1, 32>>>(cursor, 2);
    count_deg<<<(NEDG + 255) / 256, 256>>>(ei0_dst, cntt, NEDG);
    count_deg<<<(NEDG + 255) / 256, 256>>>(ei1_dst, cntu, NEDG);
    assign_off<<<(NTXN + 255) / 256, 256>>>(cntt, startt, tmpt, cursor + 0, NTXN);
    assign_off<<<(NUSR + 255) / 256, 256>>>(cntu, startu, tmpu, cursor + 1, NUSR);
    fill_perm<<<(NEDG + 255) / 256, 256>>>(ei0_src, ei0_dst, tmpt, permt, NEDG);
    fill_perm<<<(NEDG + 255) / 256, 256>>>(ei1_src, ei1_dst, tmpu, permu, NEDG);

    // 3) layers
    for (int l = 0; l < NLAY; l++) {
        agg_mean<<<(NTXN * 32 + 255) / 256, 256>>>(startt, cntt, permt, hu, aggt, NTXN);
        agg_mean<<<(NUSR * 32 + 255) / 256, 256>>>(startu, cntu, permu, ht, aggu, NUSR);

        // txn nodes: weights/bias (l,0), BN (l,1)
        {
            int lt = l * 2 + 0;
            gemm_mma<<<(NTXN + 127) / 128, 256, SMB_TOT>>>(
                aggt, ht,
                wimg + (size_t)lt * 8192,
                bl   + (size_t)lt * HDIM,
                bn_g + (size_t)(l * 2 + 1) * HDIM, bn_b + (size_t)(l * 2 + 1) * HDIM,
                bn_m + (size_t)(l * 2 + 1) * HDIM, bn_v + (size_t)(l * 2 + 1) * HDIM,
                ht, NTXN);
        }
        // user nodes: weights/bias (l,1), BN (l,0)
        {
            int lt = l * 2 + 1;
            gemm_mma<<<(NUSR + 127) / 128, 256, SMB_TOT>>>(
                aggu, hu,
                wimg + (size_t)lt * 8192,
                bl   + (size_t)lt * HDIM,
                bn_g + (size_t)(l * 2 + 0) * HDIM, bn_b + (size_t)(l * 2 + 0) * HDIM,
                bn_m + (size_t)(l * 2 + 0) * HDIM, bn_v + (size_t)(l * 2 + 0) * HDIM,
                hu, NUSR);
        }
    }

    // 4) MLP head (tensorized)
    mlp_mma<<<(NTOT + 255) / 256, 256>>>(hu, ht, w1img, b1, W2, b2, out);
}